// round 2
// baseline (speedup 1.0000x reference)
#include <cuda_runtime.h>

#define NA   768
#define NM1  767
#define NE   (768*767)      // 589056
#define DIM  64
#define NCV  50
#define NCONV 3

#define CONV_THREADS 128
#define CHUNK  16
#define SPLITS 48           // CHUNK*SPLITS == NA

// ---------------- scratch (__device__ globals; no runtime allocation) ----------
__device__ float g_rbfT[NCV * NE];   // transposed rbf: [k][e], ~118 MB
__device__ float g_h  [NA * DIM];
__device__ float g_nw [NA * DIM];
__device__ float g_agg[NA * DIM];
__device__ float g_ha [NA];

// softplus_bt(x, beta=0.5, thr=14): bx=0.5x; bx>14 ? x : softplus(bx)/0.5
__device__ __forceinline__ float softplus_half(float x) {
    float t = 0.5f * x;
    if (t > 14.0f) return x;
    return 2.0f * (fmaxf(t, 0.0f) + log1pf(__expf(-fabsf(t))));
}

// ---------------- h init: embedding gather -----------------------------------
__global__ void k_init_h(const int* __restrict__ at, const float* __restrict__ emb) {
    int idx = blockIdx.x * blockDim.x + threadIdx.x;
    if (idx < NA * DIM) {
        int i = idx >> 6;
        int c = idx & 63;
        g_h[idx] = emb[at[i] * DIM + c];
    }
}

// ---------------- rbf: exp(-(1/gap)*(d-mu_k)^2), stored transposed ------------
__global__ void k_rbf(const float* __restrict__ dist) {
    int e = blockIdx.x * blockDim.x + threadIdx.x;
    if (e >= NE) return;
    float d = dist[e];
#pragma unroll
    for (int k = 0; k < NCV; k++) {
        float mu = (float)(k * (5.0 / 49.0));
        float v = d - mu;
        g_rbfT[k * NE + e] = __expf(-9.8f * v * v);
    }
}

// ---------------- nw = h @ w1[l]; also zero agg -------------------------------
__global__ void k_nw(const float* __restrict__ w1l) {
    __shared__ float hrow[DIM];
    int i = blockIdx.x, c = threadIdx.x;
    hrow[c] = g_h[i * DIM + c];
    __syncthreads();
    float s = 0.0f;
#pragma unroll
    for (int k = 0; k < DIM; k++) s += hrow[k] * w1l[k * DIM + c];
    g_nw[i * DIM + c]  = s;
    g_agg[i * DIM + c] = 0.0f;
}

// ---------------- fused conv edge kernel (dst-major, register agg) ------------
// block: 128 threads, thread t owns dst j = blockIdx.x*128+t
// blockIdx.y selects a src chunk of CHUNK atoms; partial agg atomically added.
__global__ void __launch_bounds__(CONV_THREADS, 2)
k_conv(const float* __restrict__ pw1l, const float* __restrict__ pb1l,
       const float* __restrict__ pw2l, const float* __restrict__ pb2l) {
    extern __shared__ float sm[];
    float* s_pw1 = sm;               // 50*64 = 3200
    float* s_pw2 = sm + 3200;        // 64*64 = 4096
    float* s_pb1 = sm + 7296;        // 64
    float* s_pb2 = sm + 7360;        // 64
    float* s_t   = sm + 7424;        // 64*128 (per-thread t slice, [k][tid])

    int tid = threadIdx.x;
    for (int idx = tid; idx < 3200; idx += CONV_THREADS) s_pw1[idx] = pw1l[idx];
    for (int idx = tid; idx < 4096; idx += CONV_THREADS) s_pw2[idx] = pw2l[idx];
    if (tid < DIM) { s_pb1[tid] = pb1l[tid]; s_pb2[tid] = pb2l[tid]; }
    __syncthreads();

    int j  = blockIdx.x * CONV_THREADS + tid;
    int i0 = blockIdx.y * CHUNK;

    float acc[DIM];
#pragma unroll
    for (int c = 0; c < DIM; c++) acc[c] = 0.0f;

    for (int ii = 0; ii < CHUNK; ii++) {
        int i = i0 + ii;
        if (i == j) continue;
        int eidx = i * NM1 + j - (j > i ? 1 : 0);

        // u = rbf(e) @ pw1 + pb1   (K=50)
        float u[DIM];
#pragma unroll
        for (int c = 0; c < DIM; c++) u[c] = s_pb1[c];
#pragma unroll 2
        for (int k = 0; k < NCV; k++) {
            float rk = g_rbfT[k * NE + eidx];            // coalesced across tid
            const float4* w4 = (const float4*)(s_pw1 + k * DIM);
#pragma unroll
            for (int c4 = 0; c4 < 16; c4++) {
                float4 w = w4[c4];
                u[4*c4+0] += rk * w.x;
                u[4*c4+1] += rk * w.y;
                u[4*c4+2] += rk * w.z;
                u[4*c4+3] += rk * w.w;
            }
        }
        // softplus -> private smem slice (lets 2nd GEMM index k dynamically)
#pragma unroll
        for (int c = 0; c < DIM; c++) {
            float x = u[c];
            float t = 0.5f * x;
            float sp = (t > 14.0f) ? x
                     : 2.0f * (fmaxf(t, 0.0f) + log1pf(__expf(-fabsf(t))));
            s_t[c * CONV_THREADS + tid] = sp;
        }
        // e = t @ pw2 + pb2   (K=64)
        float ev[DIM];
#pragma unroll
        for (int c = 0; c < DIM; c++) ev[c] = s_pb2[c];
#pragma unroll 2
        for (int k = 0; k < DIM; k++) {
            float tk = s_t[k * CONV_THREADS + tid];      // conflict-free
            const float4* w4 = (const float4*)(s_pw2 + k * DIM);
#pragma unroll
            for (int c4 = 0; c4 < 16; c4++) {
                float4 w = w4[c4];
                ev[4*c4+0] += tk * w.x;
                ev[4*c4+1] += tk * w.y;
                ev[4*c4+2] += tk * w.z;
                ev[4*c4+3] += tk * w.w;
            }
        }
        // acc += nw[i] * e   (nw[i] broadcast across block)
        const float4* nw4 = (const float4*)(g_nw + i * DIM);
#pragma unroll
        for (int c4 = 0; c4 < 16; c4++) {
            float4 nv = nw4[c4];
            acc[4*c4+0] += nv.x * ev[4*c4+0];
            acc[4*c4+1] += nv.y * ev[4*c4+1];
            acc[4*c4+2] += nv.z * ev[4*c4+2];
            acc[4*c4+3] += nv.w * ev[4*c4+3];
        }
    }
#pragma unroll
    for (int c = 0; c < DIM; c++) atomicAdd(&g_agg[j * DIM + c], acc[c]);
}

// ---------------- update MLP: h += softplus(agg@qw1+qb1)@qw2+qb2 --------------
__global__ void k_update(const float* __restrict__ qw1l, const float* __restrict__ qb1l,
                         const float* __restrict__ qw2l, const float* __restrict__ qb2l) {
    __shared__ float arow[DIM];
    __shared__ float trow[DIM];
    int i = blockIdx.x, c = threadIdx.x;
    arow[c] = g_agg[i * DIM + c];
    __syncthreads();
    float s = qb1l[c];
#pragma unroll
    for (int k = 0; k < DIM; k++) s += arow[k] * qw1l[k * DIM + c];
    trow[c] = softplus_half(s);
    __syncthreads();
    float s2 = qb2l[c];
#pragma unroll
    for (int k = 0; k < DIM; k++) s2 += trow[k] * qw2l[k * DIM + c];
    g_h[i * DIM + c] += s2;
}

// ---------------- atom update: ha (N,1) ---------------------------------------
__global__ void k_atom(const float* __restrict__ au_w1, const float* __restrict__ au_b1,
                       const float* __restrict__ au_w2, const float* __restrict__ au_b2) {
    __shared__ float hrow[DIM];
    __shared__ float red[DIM];
    int i = blockIdx.x, c = threadIdx.x;
    hrow[c] = g_h[i * DIM + c];
    __syncthreads();
    float s = au_b1[c];
#pragma unroll
    for (int k = 0; k < DIM; k++) s += hrow[k] * au_w1[k * DIM + c];
    // ShiftSoftplus: softplus_bt(x,1,20) - ln2
    float sp = (s > 20.0f) ? s : (fmaxf(s, 0.0f) + log1pf(__expf(-fabsf(s))));
    sp -= 0.69314718055994530942f;
    red[c] = sp * au_w2[c];
    __syncthreads();
    if (c < 32) {
        float v = red[c] + red[c + 32];
#pragma unroll
        for (int off = 16; off; off >>= 1) v += __shfl_down_sync(0xffffffffu, v, off);
        if (c == 0) g_ha[i] = v + au_b2[0];
    }
}

// ---------------- readout over all ordered pairs ------------------------------
__global__ void __launch_bounds__(128)
k_readout(const float* __restrict__ ro_w1, const float* __restrict__ ro_b1,
          const float* __restrict__ ro_w2, const float* __restrict__ ro_b2,
          float* __restrict__ out) {
    __shared__ float s_w1[52 * DIM];   // rows: 0=ha_src, 1=ha_dst, 2..51=rbf
    __shared__ float s_b1[DIM];
    __shared__ float s_w2[DIM * 2];
    __shared__ float s_b2[2];
    int tid = threadIdx.x;
    for (int idx = tid; idx < 52 * DIM; idx += 128) s_w1[idx] = ro_w1[idx];
    if (tid < DIM)     s_b1[tid] = ro_b1[tid];
    if (tid < DIM * 2) s_w2[tid] = ro_w2[tid];
    if (tid < 2)       s_b2[tid] = ro_b2[tid];
    __syncthreads();

    int e = blockIdx.x * 128 + tid;
    if (e >= NE) return;
    int i   = e / NM1;
    int pos = e - i * NM1;
    int j   = pos + (pos >= i ? 1 : 0);
    float hi = g_ha[i], hj = g_ha[j];

    float f[DIM];
#pragma unroll
    for (int c = 0; c < DIM; c++) f[c] = s_b1[c];
    {
        const float4* wa = (const float4*)(s_w1);
        const float4* wb = (const float4*)(s_w1 + DIM);
#pragma unroll
        for (int c4 = 0; c4 < 16; c4++) {
            float4 a = wa[c4], b = wb[c4];
            f[4*c4+0] += hi * a.x + hj * b.x;
            f[4*c4+1] += hi * a.y + hj * b.y;
            f[4*c4+2] += hi * a.z + hj * b.z;
            f[4*c4+3] += hi * a.w + hj * b.w;
        }
    }
#pragma unroll 2
    for (int k = 0; k < NCV; k++) {
        float rk = g_rbfT[k * NE + e];                 // coalesced
        const float4* w4 = (const float4*)(s_w1 + (2 + k) * DIM);
#pragma unroll
        for (int c4 = 0; c4 < 16; c4++) {
            float4 w = w4[c4];
            f[4*c4+0] += rk * w.x;
            f[4*c4+1] += rk * w.y;
            f[4*c4+2] += rk * w.z;
            f[4*c4+3] += rk * w.w;
        }
    }
    float l0 = s_b2[0], l1 = s_b2[1];
#pragma unroll
    for (int c = 0; c < DIM; c++) {
        float v = fmaxf(f[c], 0.0f);                   // relu
        l0 += v * s_w2[c * 2 + 0];
        l1 += v * s_w2[c * 2 + 1];
    }
    float m  = fmaxf(l0, l1);
    float p0 = __expf(l0 - m), p1 = __expf(l1 - m);
    float inv = 1.0f / (p0 + p1);
    out[2 * e + 0] = p0 * inv;
    out[2 * e + 1] = p1 * inv;
}

// ---------------- launch ------------------------------------------------------
extern "C" void kernel_launch(void* const* d_in, const int* in_sizes, int n_in,
                              void* d_out, int out_size) {
    const int*   at    = (const int*)  d_in[0];
    const float* dist  = (const float*)d_in[1];
    // d_in[2]=src, d_in[3]=dst: implied by complete-graph closed form, unused
    const float* emb   = (const float*)d_in[4];
    const float* w1    = (const float*)d_in[5];
    const float* pw1   = (const float*)d_in[6];
    const float* pb1   = (const float*)d_in[7];
    const float* pw2   = (const float*)d_in[8];
    const float* pb2   = (const float*)d_in[9];
    const float* qw1   = (const float*)d_in[10];
    const float* qb1   = (const float*)d_in[11];
    const float* qw2   = (const float*)d_in[12];
    const float* qb2   = (const float*)d_in[13];
    const float* au_w1 = (const float*)d_in[14];
    const float* au_b1 = (const float*)d_in[15];
    const float* au_w2 = (const float*)d_in[16];
    const float* au_b2 = (const float*)d_in[17];
    const float* ro_w1 = (const float*)d_in[18];
    const float* ro_b1 = (const float*)d_in[19];
    const float* ro_w2 = (const float*)d_in[20];
    const float* ro_b2 = (const float*)d_in[21];
    float* out = (float*)d_out;

    const int conv_smem = (3200 + 4096 + 64 + 64 + 64 * CONV_THREADS) * (int)sizeof(float);
    cudaFuncSetAttribute(k_conv, cudaFuncAttributeMaxDynamicSharedMemorySize, conv_smem);

    k_init_h<<<(NA * DIM + 255) / 256, 256>>>(at, emb);
    k_rbf<<<(NE + 255) / 256, 256>>>(dist);

    for (int l = 0; l < NCONV; l++) {
        k_nw<<<NA, DIM>>>(w1 + l * DIM * DIM);
        dim3 grid(NA / CONV_THREADS, SPLITS);
        k_conv<<<grid, CONV_THREADS, conv_smem>>>(pw1 + l * NCV * DIM, pb1 + l * DIM,
                                                  pw2 + l * DIM * DIM, pb2 + l * DIM);
        k_update<<<NA, DIM>>>(qw1 + l * DIM * DIM, qb1 + l * DIM,
                              qw2 + l * DIM * DIM, qb2 + l * DIM);
    }
    k_atom<<<NA, DIM>>>(au_w1, au_b1, au_w2, au_b2);
    k_readout<<<(NE + 127) / 128, 128>>>(ro_w1, ro_b1, ro_w2, ro_b2, out);
}